// round 10
// baseline (speedup 1.0000x reference)
#include <cuda_runtime.h>
#include <cstdint>

// Problem constants (fixed by setup_inputs: N=64, T=400, D=1024, M=256)
#define NTOK 25600
#define DDIM 1024
#define MCOD 256
#define ROWS_PER_BLK 64

typedef unsigned long long u64;

// ---------------- device scratch (allocation-free per harness rules) ----------------
__device__ float    g_enorm[MCOD * DDIM];   // fp32 normalized codebook (exact pass)
__device__ uint32_t g_eq[MCOD * 256];       // int8-packed codebook, 4 k per word
__device__ float    g_escale[MCOD];         // per-code quant scale
__device__ float    g_se[MCOD];
__device__ unsigned g_semax;                // float bits, atomicMax (positive floats)
__device__ unsigned g_l1emax;               // float bits, atomicMax
__device__ int      g_counts[MCOD];
__device__ double   g_loss;

// ---------------------------------------------------------------------------
// Zero accumulators (must run every launch: graph replays reuse globals)
// ---------------------------------------------------------------------------
__global__ void vq_init() {
    int t = threadIdx.x;
    g_counts[t] = 0;
    if (t == 0) { g_loss = 0.0; g_semax = 0u; g_l1emax = 0u; }
}

// ---------------------------------------------------------------------------
// emb_norm[m] = emb[m] / (||emb[m]|| + 1e-4)  (reference rounding), se[m],
// plus the int8-quantized image of emb_norm with per-code scale and global
// worst-case stats (max scale, max L1) for the deterministic screening margin.
// ---------------------------------------------------------------------------
__global__ __launch_bounds__(256) void vq_normalize(const float* __restrict__ emb) {
    __shared__ float red[256];
    __shared__ float s_inv;
    const int m = blockIdx.x;
    const int t = threadIdx.x;

    float4 v = ((const float4*)(emb + (size_t)m * DDIM))[t];
    red[t] = v.x * v.x + v.y * v.y + v.z * v.z + v.w * v.w;
    __syncthreads();
    for (int s = 128; s > 0; s >>= 1) {
        if (t < s) red[t] += red[t + s];
        __syncthreads();
    }
    float denom = __fadd_rn(sqrtf(red[0]), 1e-4f);
    __syncthreads();

    float4 e;
    e.x = __fdiv_rn(v.x, denom);
    e.y = __fdiv_rn(v.y, denom);
    e.z = __fdiv_rn(v.z, denom);
    e.w = __fdiv_rn(v.w, denom);
    ((float4*)(g_enorm + (size_t)m * DDIM))[t] = e;

    // se = sum(e^2)
    red[t] = e.x * e.x + e.y * e.y + e.z * e.z + e.w * e.w;
    __syncthreads();
    for (int s = 128; s > 0; s >>= 1) {
        if (t < s) red[t] += red[t + s];
        __syncthreads();
    }
    if (t == 0) g_se[m] = red[0];
    __syncthreads();

    // amax(|e|) -> per-code scale
    red[t] = fmaxf(fmaxf(fabsf(e.x), fabsf(e.y)), fmaxf(fabsf(e.z), fabsf(e.w)));
    __syncthreads();
    for (int s = 128; s > 0; s >>= 1) {
        if (t < s) red[t] = fmaxf(red[t], red[t + s]);
        __syncthreads();
    }
    if (t == 0) {
        float amax = fmaxf(red[0], 1e-20f);
        float sc = amax / 127.0f;
        g_escale[m] = sc;
        s_inv = 127.0f / amax;
        atomicMax(&g_semax, __float_as_uint(sc));
    }
    __syncthreads();

    // L1(|e|) -> global max for margin
    red[t] = fabsf(e.x) + fabsf(e.y) + fabsf(e.z) + fabsf(e.w);
    __syncthreads();
    for (int s = 128; s > 0; s >>= 1) {
        if (t < s) red[t] += red[t + s];
        __syncthreads();
    }
    if (t == 0) atomicMax(&g_l1emax, __float_as_uint(red[0]));

    // quantize + pack this thread's 4 elements (k = 4t..4t+3)
    float inv = s_inv;
    int q0 = max(-127, min(127, __float2int_rn(e.x * inv)));
    int q1 = max(-127, min(127, __float2int_rn(e.y * inv)));
    int q2 = max(-127, min(127, __float2int_rn(e.z * inv)));
    int q3 = max(-127, min(127, __float2int_rn(e.w * inv)));
    g_eq[m * 256 + t] = (uint32_t)(q0 & 0xFF) | ((uint32_t)(q1 & 0xFF) << 8) |
                        ((uint32_t)(q2 & 0xFF) << 16) | ((uint32_t)(q3 & 0xFF) << 24);
}

// ---------------------------------------------------------------------------
// Main fused kernel:
//  A) per-row x stats (amax -> quant scale, L1 -> margin, sum(x^2))
//  B) int8 DP4A screening GEMM, R3 tiling: 64 rows x 256 codes, k-tiles of 32
//     (8 packed words), acc int32 [4 rows][16 codes] per thread (exact int)
//  C) screened distances (stored back into acc via bit reinterpret) +
//     per-row min; exact fp32 recheck of every code within the DETERMINISTIC
//     quantization bound; winner via atomicMin(bits(d)<<32|code) -> exact
//     argmin with lowest-index ties (same decision class as round 3)
//  D) gather + straight-through output + commitment loss + counts
// ---------------------------------------------------------------------------
__global__ __launch_bounds__(256, 2) void vq_main(const float* __restrict__ x,
                                                  const float* __restrict__ emb,
                                                  float* __restrict__ out) {
    __shared__ __align__(16) uint32_t xsq[8][ROWS_PER_BLK];  // 2KB packed x tile
    __shared__ __align__(16) uint32_t esq[8][MCOD];          // 8KB packed e tile
    __shared__ float sse[MCOD], sescale[MCOD];
    __shared__ float ssx[ROWS_PER_BLK], sscl[ROWS_PER_BLK];
    __shared__ float sinv[ROWS_PER_BLK], sl1[ROWS_PER_BLK];
    __shared__ u64   skey[ROWS_PER_BLK];
    __shared__ int   sidx[ROWS_PER_BLK];
    __shared__ float sred[256];

    const int t   = threadIdx.x;
    const int ty  = t >> 4;
    const int tx2 = t & 15;
    const size_t rowBase = (size_t)blockIdx.x * ROWS_PER_BLK;
    const float semax = __uint_as_float(g_semax);
    const float l1em  = __uint_as_float(g_l1emax);

    // ---- Phase A: row stats (4 threads per row, 256 floats each)
    {
        const int row = t >> 2, part = t & 3;
        const float* xr = x + (rowBase + row) * DDIM + part * 256;
        float am = 0.f, l1 = 0.f, sq = 0.f;
        for (int k = 0; k < 256; k += 4) {
            float4 v = *(const float4*)(xr + k);
            float a0 = fabsf(v.x), a1 = fabsf(v.y), a2 = fabsf(v.z), a3 = fabsf(v.w);
            am = fmaxf(am, fmaxf(fmaxf(a0, a1), fmaxf(a2, a3)));
            l1 += (a0 + a1) + (a2 + a3);
            sq = __fmaf_rn(v.x, v.x, sq);
            sq = __fmaf_rn(v.y, v.y, sq);
            sq = __fmaf_rn(v.z, v.z, sq);
            sq = __fmaf_rn(v.w, v.w, sq);
        }
        am = fmaxf(am, __shfl_xor_sync(0xffffffffu, am, 1));
        am = fmaxf(am, __shfl_xor_sync(0xffffffffu, am, 2));
        l1 += __shfl_xor_sync(0xffffffffu, l1, 1);
        l1 += __shfl_xor_sync(0xffffffffu, l1, 2);
        sq += __shfl_xor_sync(0xffffffffu, sq, 1);
        sq += __shfl_xor_sync(0xffffffffu, sq, 2);
        if (part == 0) {
            float amax = fmaxf(am, 1e-20f);
            ssx[row]  = sq;
            sscl[row] = amax / 127.0f;
            sinv[row] = 127.0f / amax;
            sl1[row]  = l1;
        }
    }
    sse[t] = g_se[t];
    sescale[t] = g_escale[t];
    if (t < ROWS_PER_BLK) skey[t] = ~0ull;
    __syncthreads();

    // ---- Phase B: DP4A screening GEMM
    int acc[4][16];
#pragma unroll
    for (int i = 0; i < 4; i++)
#pragma unroll
        for (int j = 0; j < 16; j++) acc[i][j] = 0;

    const int lr = t >> 2;
    const int lq = t & 3;
    const float* xld = x + (rowBase + lr) * DDIM + lq * 8;
    const uint32_t* eld = g_eq + (size_t)t * 256;
    const float xinv = sinv[lr];

    for (int k0 = 0; k0 < 32; k0++) {
        // quantize + pack 8 x floats for row lr
        float4 a = *(const float4*)(xld + k0 * 32);
        float4 b = *(const float4*)(xld + k0 * 32 + 4);
        int q0 = __float2int_rn(a.x * xinv), q1 = __float2int_rn(a.y * xinv);
        int q2 = __float2int_rn(a.z * xinv), q3 = __float2int_rn(a.w * xinv);
        int q4 = __float2int_rn(b.x * xinv), q5 = __float2int_rn(b.y * xinv);
        int q6 = __float2int_rn(b.z * xinv), q7 = __float2int_rn(b.w * xinv);
        xsq[2 * lq][lr] = (uint32_t)(q0 & 0xFF) | ((uint32_t)(q1 & 0xFF) << 8) |
                          ((uint32_t)(q2 & 0xFF) << 16) | ((uint32_t)(q3 & 0xFF) << 24);
        xsq[2 * lq + 1][lr] = (uint32_t)(q4 & 0xFF) | ((uint32_t)(q5 & 0xFF) << 8) |
                              ((uint32_t)(q6 & 0xFF) << 16) | ((uint32_t)(q7 & 0xFF) << 24);
        // e tile: thread t owns code t, 8 packed words
        uint4 e0 = *(const uint4*)(eld + k0 * 8);
        uint4 e1 = *(const uint4*)(eld + k0 * 8 + 4);
        esq[0][t] = e0.x; esq[1][t] = e0.y; esq[2][t] = e0.z; esq[3][t] = e0.w;
        esq[4][t] = e1.x; esq[5][t] = e1.y; esq[6][t] = e1.z; esq[7][t] = e1.w;
        __syncthreads();

#pragma unroll
        for (int kw = 0; kw < 8; kw++) {
            uint4 xr4 = *(const uint4*)&xsq[kw][ty * 4];
            int xi[4] = {(int)xr4.x, (int)xr4.y, (int)xr4.z, (int)xr4.w};
#pragma unroll
            for (int g = 0; g < 4; g++) {
                uint4 ep = *(const uint4*)&esq[kw][g * 64 + tx2 * 4];
#pragma unroll
                for (int i = 0; i < 4; i++) {
                    acc[i][g * 4 + 0] = __dp4a(xi[i], (int)ep.x, acc[i][g * 4 + 0]);
                    acc[i][g * 4 + 1] = __dp4a(xi[i], (int)ep.y, acc[i][g * 4 + 1]);
                    acc[i][g * 4 + 2] = __dp4a(xi[i], (int)ep.z, acc[i][g * 4 + 2]);
                    acc[i][g * 4 + 3] = __dp4a(xi[i], (int)ep.w, acc[i][g * 4 + 3]);
                }
            }
        }
        __syncthreads();
    }

    // ---- Phase C: screened distances + exact recheck
    const float sxv[4] = {ssx[ty * 4 + 0], ssx[ty * 4 + 1],
                          ssx[ty * 4 + 2], ssx[ty * 4 + 3]};
    const float rsc[4] = {sscl[ty * 4 + 0], sscl[ty * 4 + 1],
                          sscl[ty * 4 + 2], sscl[ty * 4 + 3]};
    float rmin[4] = {3.4e38f, 3.4e38f, 3.4e38f, 3.4e38f};
#pragma unroll
    for (int j = 0; j < 16; j++) {
        const int c = (j >> 2) * 64 + tx2 * 4 + (j & 3);
        const float se = sse[c];
        const float fe = 2.0f * sescale[c];
#pragma unroll
        for (int i = 0; i < 4; i++) {
            float d = (se + sxv[i]) - fe * rsc[i] * (float)acc[i][j];
            acc[i][j] = __float_as_int(d);   // store screened d in place
            rmin[i] = fminf(rmin[i], d);
        }
    }
#pragma unroll
    for (int i = 0; i < 4; i++) {
        rmin[i] = fminf(rmin[i], __shfl_xor_sync(0xffffffffu, rmin[i], 8, 16));
        rmin[i] = fminf(rmin[i], __shfl_xor_sync(0xffffffffu, rmin[i], 4, 16));
        rmin[i] = fminf(rmin[i], __shfl_xor_sync(0xffffffffu, rmin[i], 2, 16));
        rmin[i] = fminf(rmin[i], __shfl_xor_sync(0xffffffffu, rmin[i], 1, 16));
    }

#pragma unroll
    for (int i = 0; i < 4; i++) {
        const int row = ty * 4 + i;
        // deterministic quantization bound on screened distance error
        const float m1 = 0.5f * semax * sl1[row] + 0.5f * rsc[i] * l1em
                       + 256.0f * semax * rsc[i];
        const float thr = rmin[i] + 2.0f * m1 * 1.02f + 1e-2f;
        const float sxr = sxv[i];
        const float* xr = x + (rowBase + row) * DDIM;
#pragma unroll 1
        for (int j = 0; j < 16; j++) {
            if (__int_as_float(acc[i][j]) <= thr) {
                const int code = (j >> 2) * 64 + tx2 * 4 + (j & 3);
                const float* er = g_enorm + (size_t)code * DDIM;
                float d0 = 0.f, d1 = 0.f, d2 = 0.f, d3 = 0.f;
                float d4 = 0.f, d5 = 0.f, d6 = 0.f, d7 = 0.f;
                for (int k = 0; k < DDIM; k += 8) {
                    float4 va = *(const float4*)(xr + k);
                    float4 vb = *(const float4*)(er + k);
                    float4 va2 = *(const float4*)(xr + k + 4);
                    float4 vb2 = *(const float4*)(er + k + 4);
                    d0 = __fmaf_rn(va.x, vb.x, d0);
                    d1 = __fmaf_rn(va.y, vb.y, d1);
                    d2 = __fmaf_rn(va.z, vb.z, d2);
                    d3 = __fmaf_rn(va.w, vb.w, d3);
                    d4 = __fmaf_rn(va2.x, vb2.x, d4);
                    d5 = __fmaf_rn(va2.y, vb2.y, d5);
                    d6 = __fmaf_rn(va2.z, vb2.z, d6);
                    d7 = __fmaf_rn(va2.w, vb2.w, d7);
                }
                float dot = ((d0 + d1) + (d2 + d3)) + ((d4 + d5) + (d6 + d7));
                float d = __fsub_rn(__fadd_rn(sse[code], sxr),
                                    __fmul_rn(2.0f, dot));
                // distances ~1000 > 0 -> float bits are order-preserving
                u64 key = ((u64)__float_as_uint(d) << 32) | (uint32_t)code;
                atomicMin(&skey[row], key);
            }
        }
    }
    __syncthreads();

    if (t < ROWS_PER_BLK) sidx[t] = (int)(skey[t] & 0xFFFFFFFFu);
    __syncthreads();
    if (t < ROWS_PER_BLK) atomicAdd(&g_counts[sidx[t]], 1);

    // ---- Phase D: gather + straight-through output + loss (reference rounding)
    float lloss = 0.f;
    for (int r = 0; r < ROWS_PER_BLK; ++r) {
        const int idx = sidx[r];
        float4 q  = ((const float4*)(emb + (size_t)idx * DDIM))[t];
        float4 xv = ((const float4*)(x + (rowBase + r) * DDIM))[t];
        float4 o;
        {
            float st = __fadd_rn(xv.x, __fsub_rn(q.x, xv.x));
            o.x = __fmul_rn(__fadd_rn(st, q.x), 0.5f);
            float dd = __fsub_rn(xv.x, q.x);
            lloss = __fmaf_rn(dd, dd, lloss);
        }
        {
            float st = __fadd_rn(xv.y, __fsub_rn(q.y, xv.y));
            o.y = __fmul_rn(__fadd_rn(st, q.y), 0.5f);
            float dd = __fsub_rn(xv.y, q.y);
            lloss = __fmaf_rn(dd, dd, lloss);
        }
        {
            float st = __fadd_rn(xv.z, __fsub_rn(q.z, xv.z));
            o.z = __fmul_rn(__fadd_rn(st, q.z), 0.5f);
            float dd = __fsub_rn(xv.z, q.z);
            lloss = __fmaf_rn(dd, dd, lloss);
        }
        {
            float st = __fadd_rn(xv.w, __fsub_rn(q.w, xv.w));
            o.w = __fmul_rn(__fadd_rn(st, q.w), 0.5f);
            float dd = __fsub_rn(xv.w, q.w);
            lloss = __fmaf_rn(dd, dd, lloss);
        }
        ((float4*)out)[(rowBase + r) * (DDIM / 4) + t] = o;
    }

    sred[t] = lloss;
    __syncthreads();
    for (int s = 128; s > 0; s >>= 1) {
        if (t < s) sred[t] += sred[t + s];
        __syncthreads();
    }
    if (t == 0) atomicAdd(&g_loss, (double)sred[0]);
}

// ---------------------------------------------------------------------------
// Scalars: commitment_loss = mean((x-q)^2), perplexity = exp(-sum p log(p+1e-10))
// ---------------------------------------------------------------------------
__global__ void vq_finalize(float* __restrict__ out) {
    __shared__ float red[256];
    const int t = threadIdx.x;
    float p = (float)g_counts[t] / 25600.0f;
    float term = __fmul_rn(p, logf(__fadd_rn(p, 1e-10f)));
    red[t] = term;
    __syncthreads();
    for (int s = 128; s > 0; s >>= 1) {
        if (t < s) red[t] += red[t + s];
        __syncthreads();
    }
    if (t == 0) {
        out[26214400] = (float)(g_loss / 26214400.0);
        out[26214401] = expf(-red[0]);
    }
}

extern "C" void kernel_launch(void* const* d_in, const int* in_sizes, int n_in,
                              void* d_out, int out_size) {
    const float* x   = (const float*)d_in[0];
    const float* emb = (const float*)d_in[1];
    float* out = (float*)d_out;

    vq_init<<<1, 256>>>();
    vq_normalize<<<MCOD, 256>>>(emb);
    vq_main<<<NTOK / ROWS_PER_BLK, 256>>>(x, emb, out);
    vq_finalize<<<1, 256>>>(out);
}

// round 11
// speedup vs baseline: 1.3593x; 1.3593x over previous
#include <cuda_runtime.h>
#include <cstdint>

// Problem constants (fixed by setup_inputs: N=64, T=400, D=1024, M=256)
#define NTOK 25600
#define DDIM 1024
#define MCOD 256
#define RPB 32              // rows per block
#define NBLK (NTOK / RPB)   // 800 CTAs
#define KCHF 64             // k floats per chunk
#define KCHP 32             // bf16 pairs per chunk
#define NCHK (DDIM / KCHF)  // 16 chunks
#define NPAIR 512           // pairs per code row
#define MARGIN 1.5f

typedef unsigned long long u64;

// ---------------- packed bf16x2 helpers (sm_80+, not "a"-gated) ----------------
static __device__ __forceinline__ uint32_t bf2(float lo, float hi) {
    uint32_t r;  // cvt packs first source into the UPPER half
    asm("cvt.rn.bf16x2.f32 %0, %1, %2;" : "=r"(r) : "f"(hi), "f"(lo));
    return r;
}
static __device__ __forceinline__ uint32_t bffma2(uint32_t a, uint32_t b, uint32_t c) {
    uint32_t d;
    asm("fma.rn.bf16x2 %0, %1, %2, %3;" : "=r"(d) : "r"(a), "r"(b), "r"(c));
    return d;
}

// ---------------- device scratch (allocation-free per harness rules) ----------------
__device__ float    g_enorm[MCOD * DDIM];   // fp32 normalized codebook (exact pass)
__device__ uint32_t g_ebf[MCOD * NPAIR];    // packed bf16 pairs of g_enorm
__device__ float    g_se[MCOD];
__device__ int      g_counts[MCOD];
__device__ double   g_loss;

// ---------------------------------------------------------------------------
// Zero accumulators (must run every launch: graph replays reuse globals)
// ---------------------------------------------------------------------------
__global__ void vq_init() {
    int t = threadIdx.x;
    g_counts[t] = 0;
    if (t == 0) g_loss = 0.0;
}

// ---------------------------------------------------------------------------
// emb_norm[m] = emb[m] / (||emb[m]|| + 1e-4);  se[m] = sum(emb_norm[m]^2)
// Also emits the packed bf16 image of emb_norm for the screening GEMM.
// ---------------------------------------------------------------------------
__global__ __launch_bounds__(256) void vq_normalize(const float* __restrict__ emb) {
    __shared__ float red[256];
    const int m = blockIdx.x;
    const int t = threadIdx.x;

    float4 v = ((const float4*)(emb + (size_t)m * DDIM))[t];
    red[t] = v.x * v.x + v.y * v.y + v.z * v.z + v.w * v.w;
    __syncthreads();
    for (int s = 128; s > 0; s >>= 1) {
        if (t < s) red[t] += red[t + s];
        __syncthreads();
    }
    float denom = __fadd_rn(sqrtf(red[0]), 1e-4f);
    __syncthreads();

    float4 e;
    e.x = __fdiv_rn(v.x, denom);
    e.y = __fdiv_rn(v.y, denom);
    e.z = __fdiv_rn(v.z, denom);
    e.w = __fdiv_rn(v.w, denom);
    ((float4*)(g_enorm + (size_t)m * DDIM))[t] = e;

    // packed bf16 pairs (elements 4t..4t+3 -> pair indices 2t, 2t+1)
    g_ebf[(size_t)m * NPAIR + 2 * t]     = bf2(e.x, e.y);
    g_ebf[(size_t)m * NPAIR + 2 * t + 1] = bf2(e.z, e.w);

    red[t] = e.x * e.x + e.y * e.y + e.z * e.z + e.w * e.w;
    __syncthreads();
    for (int s = 128; s > 0; s >>= 1) {
        if (t < s) red[t] += red[t + s];
        __syncthreads();
    }
    if (t == 0) g_se[m] = red[0];
}

// ---------------------------------------------------------------------------
// Main fused kernel (spill-free HFMA2 redesign of the R7 architecture):
//  A) per-row sum(x^2)
//  B) bf16 HFMA2 screening GEMM: CTA tile 32 rows x 256 codes; thread tile
//     2 rows x 16 codes (accb 32 regs + accf 32 regs -> NO spills); K in 16
//     chunks of 64, bf16 accumulators flushed to fp32 masters per chunk
//  C) screened distances + per-row min (shfl); exact fp32 recheck of every
//     code within MARGIN; winner via atomicMin(bits(d)<<32|code) -> exact
//     argmin with lowest-index ties (same decision class as round 3)
//  D) gather + straight-through output + commitment loss + counts
// Thread layout: 256 threads = 16 ty (row pairs) x 16 tx2 (code groups).
// ---------------------------------------------------------------------------
__global__ __launch_bounds__(256, 2) void vq_main(const float* __restrict__ x,
                                                  const float* __restrict__ emb,
                                                  float* __restrict__ out) {
    __shared__ __align__(16) uint32_t xsb[KCHP][RPB];   // 4KB packed x tile
    __shared__ __align__(16) uint32_t esb[KCHP][MCOD];  // 32KB packed e tile
    __shared__ float sse[MCOD];
    __shared__ float ssx[RPB];
    __shared__ u64   skey[RPB];
    __shared__ int   sidx[RPB];
    __shared__ float sred[256];

    const int t   = threadIdx.x;
    const int ty  = t >> 4;
    const int tx2 = t & 15;
    const size_t rowBase = (size_t)blockIdx.x * RPB;

    // ---- Phase A: sum(x^2), 8 threads per row (128 floats each)
    {
        const int row = t >> 3, part = t & 7;
        const float* xr = x + (rowBase + row) * DDIM + part * 128;
        float sq = 0.f;
        for (int k = 0; k < 128; k += 4) {
            float4 v = *(const float4*)(xr + k);
            sq = __fmaf_rn(v.x, v.x, sq);
            sq = __fmaf_rn(v.y, v.y, sq);
            sq = __fmaf_rn(v.z, v.z, sq);
            sq = __fmaf_rn(v.w, v.w, sq);
        }
        sq += __shfl_xor_sync(0xffffffffu, sq, 1);
        sq += __shfl_xor_sync(0xffffffffu, sq, 2);
        sq += __shfl_xor_sync(0xffffffffu, sq, 4);
        if (part == 0) ssx[row] = sq;
    }
    sse[t] = g_se[t];
    if (t < RPB) skey[t] = ~0ull;
    __syncthreads();

    // ---- Phase B: HFMA2 screening GEMM
    float accf[2][16];
#pragma unroll
    for (int i = 0; i < 2; i++)
#pragma unroll
        for (int j = 0; j < 16; j++) accf[i][j] = 0.f;

    const int lr = t >> 3;          // x-load row (0..31)
    const int lq = t & 7;           // x-load 8-float group
    const float* xld = x + (rowBase + lr) * DDIM + lq * 8;
    const uint32_t* eld = g_ebf + (size_t)t * NPAIR;   // thread owns code t

    for (int ch = 0; ch < NCHK; ch++) {
        // pack 8 x floats -> 4 bf16 pairs
        float4 a = *(const float4*)(xld + ch * KCHF);
        float4 b = *(const float4*)(xld + ch * KCHF + 4);
        xsb[lq * 4 + 0][lr] = bf2(a.x, a.y);
        xsb[lq * 4 + 1][lr] = bf2(a.z, a.w);
        xsb[lq * 4 + 2][lr] = bf2(b.x, b.y);
        xsb[lq * 4 + 3][lr] = bf2(b.z, b.w);
        // e tile: 32 pairs for code t
#pragma unroll
        for (int q = 0; q < 8; q++) {
            uint4 ev = *(const uint4*)(eld + ch * KCHP + q * 4);
            esb[q * 4 + 0][t] = ev.x;
            esb[q * 4 + 1][t] = ev.y;
            esb[q * 4 + 2][t] = ev.z;
            esb[q * 4 + 3][t] = ev.w;
        }
        __syncthreads();

        uint32_t accb[2][16];
#pragma unroll
        for (int i = 0; i < 2; i++)
#pragma unroll
            for (int j = 0; j < 16; j++) accb[i][j] = 0u;

#pragma unroll
        for (int kk = 0; kk < KCHP; kk++) {
            uint2 xp = *(const uint2*)&xsb[kk][2 * ty];   // rows 2ty, 2ty+1
#pragma unroll
            for (int g = 0; g < 4; g++) {
                uint4 ep = *(const uint4*)&esb[kk][g * 64 + tx2 * 4];
                accb[0][g * 4 + 0] = bffma2(xp.x, ep.x, accb[0][g * 4 + 0]);
                accb[0][g * 4 + 1] = bffma2(xp.x, ep.y, accb[0][g * 4 + 1]);
                accb[0][g * 4 + 2] = bffma2(xp.x, ep.z, accb[0][g * 4 + 2]);
                accb[0][g * 4 + 3] = bffma2(xp.x, ep.w, accb[0][g * 4 + 3]);
                accb[1][g * 4 + 0] = bffma2(xp.y, ep.x, accb[1][g * 4 + 0]);
                accb[1][g * 4 + 1] = bffma2(xp.y, ep.y, accb[1][g * 4 + 1]);
                accb[1][g * 4 + 2] = bffma2(xp.y, ep.z, accb[1][g * 4 + 2]);
                accb[1][g * 4 + 3] = bffma2(xp.y, ep.w, accb[1][g * 4 + 3]);
            }
        }

        // flush bf16 accumulators (even-k lo lane, odd-k hi lane) to fp32
#pragma unroll
        for (int i = 0; i < 2; i++)
#pragma unroll
            for (int j = 0; j < 16; j++) {
                uint32_t p = accb[i][j];
                accf[i][j] += __uint_as_float(p << 16);
                accf[i][j] += __uint_as_float(p & 0xFFFF0000u);
            }
        __syncthreads();
    }

    // ---- Phase C: screened distances + per-row min + exact recheck
    const int r0 = 2 * ty, r1 = 2 * ty + 1;
    const float sx0 = ssx[r0], sx1 = ssx[r1];
    float mn0 = 3.4e38f, mn1 = 3.4e38f;
#pragma unroll
    for (int j = 0; j < 16; j++) {
        const int c = (j >> 2) * 64 + tx2 * 4 + (j & 3);
        const float se = sse[c];
        float d0 = (se + sx0) - 2.0f * accf[0][j];
        float d1 = (se + sx1) - 2.0f * accf[1][j];
        accf[0][j] = d0;
        accf[1][j] = d1;
        mn0 = fminf(mn0, d0);
        mn1 = fminf(mn1, d1);
    }
    mn0 = fminf(mn0, __shfl_xor_sync(0xffffffffu, mn0, 8, 16));
    mn0 = fminf(mn0, __shfl_xor_sync(0xffffffffu, mn0, 4, 16));
    mn0 = fminf(mn0, __shfl_xor_sync(0xffffffffu, mn0, 2, 16));
    mn0 = fminf(mn0, __shfl_xor_sync(0xffffffffu, mn0, 1, 16));
    mn1 = fminf(mn1, __shfl_xor_sync(0xffffffffu, mn1, 8, 16));
    mn1 = fminf(mn1, __shfl_xor_sync(0xffffffffu, mn1, 4, 16));
    mn1 = fminf(mn1, __shfl_xor_sync(0xffffffffu, mn1, 2, 16));
    mn1 = fminf(mn1, __shfl_xor_sync(0xffffffffu, mn1, 1, 16));

#pragma unroll
    for (int i = 0; i < 2; i++) {
        const int row = 2 * ty + i;
        const float thr = (i == 0 ? mn0 : mn1) + MARGIN;
        const float sxr = (i == 0 ? sx0 : sx1);
        const float* xr = x + (rowBase + row) * DDIM;
#pragma unroll 1
        for (int j = 0; j < 16; j++) {
            if (accf[i][j] <= thr) {
                const int code = (j >> 2) * 64 + tx2 * 4 + (j & 3);
                const float* er = g_enorm + (size_t)code * DDIM;
                float d0 = 0.f, d1 = 0.f, d2 = 0.f, d3 = 0.f;
                float d4 = 0.f, d5 = 0.f, d6 = 0.f, d7 = 0.f;
                for (int k = 0; k < DDIM; k += 8) {
                    float4 va = *(const float4*)(xr + k);
                    float4 vb = *(const float4*)(er + k);
                    float4 va2 = *(const float4*)(xr + k + 4);
                    float4 vb2 = *(const float4*)(er + k + 4);
                    d0 = __fmaf_rn(va.x, vb.x, d0);
                    d1 = __fmaf_rn(va.y, vb.y, d1);
                    d2 = __fmaf_rn(va.z, vb.z, d2);
                    d3 = __fmaf_rn(va.w, vb.w, d3);
                    d4 = __fmaf_rn(va2.x, vb2.x, d4);
                    d5 = __fmaf_rn(va2.y, vb2.y, d5);
                    d6 = __fmaf_rn(va2.z, vb2.z, d6);
                    d7 = __fmaf_rn(va2.w, vb2.w, d7);
                }
                float dot = ((d0 + d1) + (d2 + d3)) + ((d4 + d5) + (d6 + d7));
                float d = __fsub_rn(__fadd_rn(sse[code], sxr),
                                    __fmul_rn(2.0f, dot));
                // distances ~1000 > 0 -> float bits are order-preserving
                u64 key = ((u64)__float_as_uint(d) << 32) | (uint32_t)code;
                atomicMin(&skey[row], key);
            }
        }
    }
    __syncthreads();

    if (t < RPB) sidx[t] = (int)(skey[t] & 0xFFFFFFFFu);
    __syncthreads();
    if (t < RPB) atomicAdd(&g_counts[sidx[t]], 1);

    // ---- Phase D: gather + straight-through output + loss (reference rounding)
    float lloss = 0.f;
    for (int r = 0; r < RPB; ++r) {
        const int idx = sidx[r];
        float4 q  = ((const float4*)(emb + (size_t)idx * DDIM))[t];
        float4 xv = ((const float4*)(x + (rowBase + r) * DDIM))[t];
        float4 o;
        {
            float st = __fadd_rn(xv.x, __fsub_rn(q.x, xv.x));
            o.x = __fmul_rn(__fadd_rn(st, q.x), 0.5f);
            float dd = __fsub_rn(xv.x, q.x);
            lloss = __fmaf_rn(dd, dd, lloss);
        }
        {
            float st = __fadd_rn(xv.y, __fsub_rn(q.y, xv.y));
            o.y = __fmul_rn(__fadd_rn(st, q.y), 0.5f);
            float dd = __fsub_rn(xv.y, q.y);
            lloss = __fmaf_rn(dd, dd, lloss);
        }
        {
            float st = __fadd_rn(xv.z, __fsub_rn(q.z, xv.z));
            o.z = __fmul_rn(__fadd_rn(st, q.z), 0.5f);
            float dd = __fsub_rn(xv.z, q.z);
            lloss = __fmaf_rn(dd, dd, lloss);
        }
        {
            float st = __fadd_rn(xv.w, __fsub_rn(q.w, xv.w));
            o.w = __fmul_rn(__fadd_rn(st, q.w), 0.5f);
            float dd = __fsub_rn(xv.w, q.w);
            lloss = __fmaf_rn(dd, dd, lloss);
        }
        ((float4*)out)[(rowBase + r) * (DDIM / 4) + t] = o;
    }

    sred[t] = lloss;
    __syncthreads();
    for (int s = 128; s > 0; s >>= 1) {
        if (t < s) sred[t] += sred[t + s];
        __syncthreads();
    }
    if (t == 0) atomicAdd(&g_loss, (double)sred[0]);
}

// ---------------------------------------------------------------------------
// Scalars: commitment_loss = mean((x-q)^2), perplexity = exp(-sum p log(p+1e-10))
// ---------------------------------------------------------------------------
__global__ void vq_finalize(float* __restrict__ out) {
    __shared__ float red[256];
    const int t = threadIdx.x;
    float p = (float)g_counts[t] / 25600.0f;
    float term = __fmul_rn(p, logf(__fadd_rn(p, 1e-10f)));
    red[t] = term;
    __syncthreads();
    for (int s = 128; s > 0; s >>= 1) {
        if (t < s) red[t] += red[t + s];
        __syncthreads();
    }
    if (t == 0) {
        out[26214400] = (float)(g_loss / 26214400.0);
        out[26214401] = expf(-red[0]);
    }
}

extern "C" void kernel_launch(void* const* d_in, const int* in_sizes, int n_in,
                              void* d_out, int out_size) {
    const float* x   = (const float*)d_in[0];
    const float* emb = (const float*)d_in[1];
    float* out = (float*)d_out;

    vq_init<<<1, 256>>>();
    vq_normalize<<<MCOD, 256>>>(emb);
    vq_main<<<NBLK, 256>>>(x, emb, out);
    vq_finalize<<<1, 256>>>(out);
}

// round 12
// speedup vs baseline: 4.4406x; 3.2669x over previous
#include <cuda_runtime.h>
#include <cstdint>

// Problem constants (fixed by setup_inputs: N=64, T=400, D=1024, M=256)
#define NTOK 25600
#define DDIM 1024
#define MCOD 256
#define ROWS_PER_BLK 64
#define KC 16
#define XLD 68  // padded row stride for xs tile (bank-conflict mitigation)

// ---------------- device scratch (allocation-free per harness rules) ----------------
__device__ float  g_enorm[MCOD * DDIM];
__device__ float  g_se[MCOD];
__device__ int    g_counts[MCOD];
__device__ double g_loss;

// ---------------------------------------------------------------------------
// emb_norm[m] = emb[m] / (||emb[m]|| + 1e-4);  se[m] = sum(emb_norm[m]^2)
// Replicates reference rounding: fp32 sum -> sqrtf (IEEE) -> +1e-4 -> IEEE div
// Block 0 additionally zeroes the cross-launch accumulators (graph replays).
// ---------------------------------------------------------------------------
__global__ __launch_bounds__(256) void vq_normalize(const float* __restrict__ emb) {
    __shared__ float red[256];
    const int m = blockIdx.x;
    const int t = threadIdx.x;

    if (m == 0) {             // fold vq_init: counts/loss reset before vq_main
        g_counts[t] = 0;
        if (t == 0) g_loss = 0.0;
    }

    float4 v = ((const float4*)(emb + (size_t)m * DDIM))[t];
    float p = v.x * v.x + v.y * v.y + v.z * v.z + v.w * v.w;
    red[t] = p;
    __syncthreads();
    for (int s = 128; s > 0; s >>= 1) {
        if (t < s) red[t] += red[t + s];
        __syncthreads();
    }
    float denom = __fadd_rn(sqrtf(red[0]), 1e-4f);
    __syncthreads();

    float4 e;
    e.x = __fdiv_rn(v.x, denom);
    e.y = __fdiv_rn(v.y, denom);
    e.z = __fdiv_rn(v.z, denom);
    e.w = __fdiv_rn(v.w, denom);
    ((float4*)(g_enorm + (size_t)m * DDIM))[t] = e;

    float p2 = e.x * e.x + e.y * e.y + e.z * e.z + e.w * e.w;
    red[t] = p2;
    __syncthreads();
    for (int s = 128; s > 0; s >>= 1) {
        if (t < s) red[t] += red[t + s];
        __syncthreads();
    }
    if (t == 0) g_se[m] = red[0];
}

// ---------------------------------------------------------------------------
// Fused: distances GEMM (64 rows x 256 codes per block, scalar FFMA) + argmin
// (reference fp32 rounding + lowest-index tiebreak) + gather + ST output +
// commitment loss partial + code counts.
// Thread layout: 256 threads = 16 ty (row groups of 4) x 16 tx2 (code groups
// of 16).  acc[4 rows][16 codes] register microkernel; 64 FFMA per k
// (sum(x^2) hoisted to the load phase -- row-constant, argmin-safe).
// ---------------------------------------------------------------------------
__global__ __launch_bounds__(256, 2) void vq_main(const float* __restrict__ x,
                                                  const float* __restrict__ emb,
                                                  float* __restrict__ out) {
    __shared__ __align__(16) float xs[KC][XLD];
    __shared__ __align__(16) float es[KC][MCOD];
    __shared__ float ssx[ROWS_PER_BLK];
    __shared__ int   sidx[ROWS_PER_BLK];
    __shared__ float sred[256];

    const int t   = threadIdx.x;
    const int ty  = t >> 4;
    const int tx2 = t & 15;
    const size_t rowBase = (size_t)blockIdx.x * ROWS_PER_BLK;

    float acc[4][16];
#pragma unroll
    for (int i = 0; i < 4; i++)
#pragma unroll
        for (int j = 0; j < 16; j++) acc[i][j] = 0.f;

    // Tile-load mapping: x tile -> each thread one float4 (row lr, quad lq);
    // e tile -> thread t owns code row t (16 contiguous floats per chunk).
    const int lr = t >> 2;
    const int lq = t & 3;
    const float* xld = x + (rowBase + lr) * DDIM + lq * 4;
    const float* eld = g_enorm + (size_t)t * DDIM;
    float sxp = 0.f;   // partial sum(x^2) for row lr (this thread's quads)

    for (int k0 = 0; k0 < DDIM; k0 += KC) {
        float4 xv = *(const float4*)(xld + k0);
        sxp = __fmaf_rn(xv.x, xv.x, sxp);
        sxp = __fmaf_rn(xv.y, xv.y, sxp);
        sxp = __fmaf_rn(xv.z, xv.z, sxp);
        sxp = __fmaf_rn(xv.w, xv.w, sxp);
        xs[lq * 4 + 0][lr] = xv.x;
        xs[lq * 4 + 1][lr] = xv.y;
        xs[lq * 4 + 2][lr] = xv.z;
        xs[lq * 4 + 3][lr] = xv.w;
#pragma unroll
        for (int q = 0; q < 4; q++) {
            float4 ev = *(const float4*)(eld + k0 + q * 4);
            es[q * 4 + 0][t] = ev.x;
            es[q * 4 + 1][t] = ev.y;
            es[q * 4 + 2][t] = ev.z;
            es[q * 4 + 3][t] = ev.w;
        }
        __syncthreads();

#pragma unroll
        for (int k = 0; k < KC; k++) {
            float4 xr4 = *(const float4*)&xs[k][ty * 4];
            float xr[4] = {xr4.x, xr4.y, xr4.z, xr4.w};
#pragma unroll
            for (int g = 0; g < 4; g++) {
                float4 er4 = *(const float4*)&es[k][g * 64 + tx2 * 4];
                float er[4] = {er4.x, er4.y, er4.z, er4.w};
#pragma unroll
                for (int i = 0; i < 4; i++)
#pragma unroll
                    for (int j = 0; j < 4; j++)
                        acc[i][g * 4 + j] = __fmaf_rn(xr[i], er[j], acc[i][g * 4 + j]);
            }
        }
        __syncthreads();
    }

    // Combine the 4 quad-partials of sum(x^2) for row lr (lanes t&~3 .. t|3).
    sxp += __shfl_xor_sync(0xffffffffu, sxp, 1);
    sxp += __shfl_xor_sync(0xffffffffu, sxp, 2);
    if (lq == 0) ssx[lr] = sxp;
    __syncthreads();

    const float sx[4] = {ssx[ty * 4 + 0], ssx[ty * 4 + 1],
                         ssx[ty * 4 + 2], ssx[ty * 4 + 3]};

    // Per-thread argmin over its 16 codes using reference rounding:
    //   d = fl( fl(se + sx) - fl(2*dot) ), lowest index wins ties.
    float bestD[4] = {3.4e38f, 3.4e38f, 3.4e38f, 3.4e38f};
    int   bestI[4] = {0, 0, 0, 0};
#pragma unroll
    for (int g = 0; g < 4; g++) {
#pragma unroll
        for (int j = 0; j < 4; j++) {
            const int cod = g * 64 + tx2 * 4 + j;
            const float sev = g_se[cod];
#pragma unroll
            for (int i = 0; i < 4; i++) {
                float d = __fsub_rn(__fadd_rn(sev, sx[i]),
                                    __fmul_rn(2.0f, acc[i][g * 4 + j]));
                if (d < bestD[i] || (d == bestD[i] && cod < bestI[i])) {
                    bestD[i] = d;
                    bestI[i] = cod;
                }
            }
        }
    }

    // Reduce across the 16 tx2 lanes (contiguous half-warp segments).
#pragma unroll
    for (int i = 0; i < 4; i++) {
        float d = bestD[i];
        int   bi = bestI[i];
        for (int off = 8; off > 0; off >>= 1) {
            float od = __shfl_down_sync(0xffffffffu, d, off, 16);
            int   oi = __shfl_down_sync(0xffffffffu, bi, off, 16);
            if (od < d || (od == d && oi < bi)) { d = od; bi = oi; }
        }
        if (tx2 == 0) sidx[ty * 4 + i] = bi;
    }
    __syncthreads();

    if (t < ROWS_PER_BLK) atomicAdd(&g_counts[sidx[t]], 1);

    // Gather + straight-through output + loss.
    // quantized_ = fl( fl( fl(x + fl(q-x)) + q ) * 0.5 )  (exactly as reference)
    float lloss = 0.f;
    for (int r = 0; r < ROWS_PER_BLK; ++r) {
        const int idx = sidx[r];
        float4 q  = ((const float4*)(emb + (size_t)idx * DDIM))[t];
        float4 xv = ((const float4*)(x + (rowBase + r) * DDIM))[t];
        float4 o;
        {
            float st = __fadd_rn(xv.x, __fsub_rn(q.x, xv.x));
            o.x = __fmul_rn(__fadd_rn(st, q.x), 0.5f);
            float dd = __fsub_rn(xv.x, q.x);
            lloss = __fmaf_rn(dd, dd, lloss);
        }
        {
            float st = __fadd_rn(xv.y, __fsub_rn(q.y, xv.y));
            o.y = __fmul_rn(__fadd_rn(st, q.y), 0.5f);
            float dd = __fsub_rn(xv.y, q.y);
            lloss = __fmaf_rn(dd, dd, lloss);
        }
        {
            float st = __fadd_rn(xv.z, __fsub_rn(q.z, xv.z));
            o.z = __fmul_rn(__fadd_rn(st, q.z), 0.5f);
            float dd = __fsub_rn(xv.z, q.z);
            lloss = __fmaf_rn(dd, dd, lloss);
        }
        {
            float st = __fadd_rn(xv.w, __fsub_rn(q.w, xv.w));
            o.w = __fmul_rn(__fadd_rn(st, q.w), 0.5f);
            float dd = __fsub_rn(xv.w, q.w);
            lloss = __fmaf_rn(dd, dd, lloss);
        }
        ((float4*)out)[(rowBase + r) * (DDIM / 4) + t] = o;
    }

    sred[t] = lloss;
    __syncthreads();
    for (int s = 128; s > 0; s >>= 1) {
        if (t < s) sred[t] += sred[t + s];
        __syncthreads();
    }
    if (t == 0) atomicAdd(&g_loss, (double)sred[0]);
}

// ---------------------------------------------------------------------------
// Scalars: commitment_loss = mean((x-q)^2), perplexity = exp(-sum p log(p+1e-10))
// ---------------------------------------------------------------------------
__global__ void vq_finalize(float* __restrict__ out) {
    __shared__ float red[256];
    const int t = threadIdx.x;
    float p = (float)g_counts[t] / 25600.0f;
    float term = __fmul_rn(p, logf(__fadd_rn(p, 1e-10f)));
    red[t] = term;
    __syncthreads();
    for (int s = 128; s > 0; s >>= 1) {
        if (t < s) red[t] += red[t + s];
        __syncthreads();
    }
    if (t == 0) {
        out[26214400] = (float)(g_loss / 26214400.0);
        out[26214401] = expf(-red[0]);
    }
}

extern "C" void kernel_launch(void* const* d_in, const int* in_sizes, int n_in,
                              void* d_out, int out_size) {
    const float* x   = (const float*)d_in[0];
    const float* emb = (const float*)d_in[1];
    float* out = (float*)d_out;

    vq_normalize<<<MCOD, 256>>>(emb);
    vq_main<<<NTOK / ROWS_PER_BLK, 256>>>(x, emb, out);
    vq_finalize<<<1, 256>>>(out);
}